// round 2
// baseline (speedup 1.0000x reference)
#include <cuda_runtime.h>
#include <float.h>

#define N_NODES 50000
#define DEG     32
#define WID     128
#define BATCH   4096
#define AS_LD   132
#define NTHREADS 512

// ---------------- device scratch ----------------
__device__ int   g_winner[N_NODES];
__device__ float g_Mb[BATCH * WID];     // relu(feats @ Wa^T + ba)
__device__ float g_Fh[BATCH * WID];     // feats @ Wlh^T
__device__ float g_H1[N_NODES * WID];   // layer-1 output (only batch rows valid/needed)
__device__ float g_M2[N_NODES * WID];   // relu(H1 @ Wa^T + ba)
__device__ float g_WaT[WID * WID];      // k-major transposed weights
__device__ float g_WlhT[WID * WID];
__device__ float g_WlaT[WID * WID];

typedef unsigned long long u64;

__device__ __forceinline__ u64 f2pack(float lo, float hi) {
    u64 r; asm("mov.b64 %0, {%1, %2};" : "=l"(r) : "f"(lo), "f"(hi)); return r;
}
__device__ __forceinline__ void f2unpack(u64 v, float& lo, float& hi) {
    asm("mov.b64 {%0, %1}, %2;" : "=f"(lo), "=f"(hi) : "l"(v));
}
__device__ __forceinline__ void f2fma(u64& c, u64 a, u64 b) {
    asm("fma.rn.f32x2 %0, %1, %2, %0;" : "+l"(c) : "l"(a), "l"(b));
}

// ---------------- 128x128x128 tile GEMM, 512 threads ----------------
// thread: tx = tid&7 (cols tx*16..+15), ty = tid>>3 (rows ty*2, ty*2+1)
__device__ __forceinline__ void gemm128(const float* __restrict__ As,
                                        const float* __restrict__ Wt,
                                        u64 C[2][8], int tx, int ty) {
    const float* a0p = As + (ty * 2) * AS_LD;
    const float* a1p = As + (ty * 2 + 1) * AS_LD;
#pragma unroll 2
    for (int k = 0; k < WID; ++k) {
        const ulonglong2* bp = (const ulonglong2*)(Wt + k * WID + tx * 16);
        ulonglong2 b01 = bp[0], b23 = bp[1], b45 = bp[2], b67 = bp[3];
        u64 bb[8] = { b01.x, b01.y, b23.x, b23.y, b45.x, b45.y, b67.x, b67.y };
        float a0 = a0p[k], a1 = a1p[k];
        u64 aa0 = f2pack(a0, a0), aa1 = f2pack(a1, a1);
#pragma unroll
        for (int j = 0; j < 8; ++j) { f2fma(C[0][j], aa0, bb[j]); f2fma(C[1][j], aa1, bb[j]); }
    }
}

__device__ __forceinline__ void zeroC(u64 C[2][8]) {
#pragma unroll
    for (int i = 0; i < 2; ++i)
#pragma unroll
        for (int j = 0; j < 8; ++j) C[i][j] = 0ull;
}

__device__ __forceinline__ void load_weights(float* Wt, const float* __restrict__ src) {
    for (int e = threadIdx.x; e < WID * WID / 4; e += NTHREADS)
        *(float4*)(Wt + e * 4) = *(const float4*)(src + e * 4);
}

__device__ __forceinline__ float rowsum8(float s) {   // sum over 8-lane row group
    s += __shfl_xor_sync(0xffffffffu, s, 1);
    s += __shfl_xor_sync(0xffffffffu, s, 2);
    s += __shfl_xor_sync(0xffffffffu, s, 4);
    return s;
}

// ---------------- setup ----------------
__global__ void k_init(const float* __restrict__ W_agg, const float* __restrict__ W_lin) {
    int t = blockIdx.x * NTHREADS + threadIdx.x;
    if (t < N_NODES) g_winner[t] = -1;
    if (t < WID * WID) {
        int k = t >> 7, d = t & 127;
        g_WaT[t]  = W_agg[d * WID + k];
        g_WlhT[t] = W_lin[d * (2 * WID) + k];
        g_WlaT[t] = W_lin[d * (2 * WID) + WID + k];
    }
}

__global__ void k_scatter(const int* __restrict__ node_idx) {
    int i = blockIdx.x * NTHREADS + threadIdx.x;
    if (i < BATCH) atomicMax(&g_winner[node_idx[i]], i);
}

// ---------------- batch precompute: Mb and Fh ----------------
__global__ void __launch_bounds__(NTHREADS, 1)
k_batch(const float* __restrict__ feats, const float* __restrict__ b_agg) {
    extern __shared__ float sm[];
    float* As = sm;
    float* Wt = sm + WID * AS_LD;
    const int tid = threadIdx.x;
    const int tx = tid & 7, ty = tid >> 3;
    const int r0 = blockIdx.x * WID;

    for (int e = tid; e < WID * WID / 4; e += NTHREADS) {
        int row = e >> 5, c4 = (e & 31) << 2;
        *(float4*)(As + row * AS_LD + c4) = *(const float4*)(feats + (r0 + row) * WID + c4);
    }
    load_weights(Wt, g_WaT);
    __syncthreads();

    u64 C[2][8];
    zeroC(C);
    gemm128(As, Wt, C, tx, ty);

    float bav[16];
#pragma unroll
    for (int q = 0; q < 4; ++q) {
        float4 b = *(const float4*)(b_agg + tx * 16 + q * 4);
        bav[q*4+0]=b.x; bav[q*4+1]=b.y; bav[q*4+2]=b.z; bav[q*4+3]=b.w;
    }
#pragma unroll
    for (int i = 0; i < 2; ++i) {
        int row = ty * 2 + i;
        float v[16];
#pragma unroll
        for (int j = 0; j < 8; ++j) f2unpack(C[i][j], v[2*j], v[2*j+1]);
        float* dst = g_Mb + (r0 + row) * WID + tx * 16;
#pragma unroll
        for (int q = 0; q < 4; ++q)
            *(float4*)(dst + q*4) = make_float4(fmaxf(v[q*4+0]+bav[q*4+0],0.f),
                                                fmaxf(v[q*4+1]+bav[q*4+1],0.f),
                                                fmaxf(v[q*4+2]+bav[q*4+2],0.f),
                                                fmaxf(v[q*4+3]+bav[q*4+3],0.f));
    }
    __syncthreads();
    load_weights(Wt, g_WlhT);
    __syncthreads();

    zeroC(C);
    gemm128(As, Wt, C, tx, ty);
#pragma unroll
    for (int i = 0; i < 2; ++i) {
        int row = ty * 2 + i;
        float v[16];
#pragma unroll
        for (int j = 0; j < 8; ++j) f2unpack(C[i][j], v[2*j], v[2*j+1]);
        float* dst = g_Fh + (r0 + row) * WID + tx * 16;
#pragma unroll
        for (int q = 0; q < 4; ++q)
            *(float4*)(dst + q*4) = make_float4(v[q*4], v[q*4+1], v[q*4+2], v[q*4+3]);
    }
}

// ---------------- main fused: layer1 (agg+combine+norm) + layer2 M2 ----------------
__global__ void __launch_bounds__(NTHREADS, 1)
k_main(const int* __restrict__ nbd, const float* __restrict__ b_agg,
       const float* __restrict__ b_lin) {
    extern __shared__ float sm[];
    float* As = sm;
    float* Wt = sm + WID * AS_LD;
    const int tid = threadIdx.x;
    const int lane = tid & 31, warp = tid >> 5;      // 16 warps
    const int tx = tid & 7, ty = tid >> 3;
    const int r0 = blockIdx.x * WID;

    float4 bag = *(const float4*)(b_agg + lane * 4);
    float4 cvec = make_float4(fmaxf(bag.x,0.f), fmaxf(bag.y,0.f),
                              fmaxf(bag.z,0.f), fmaxf(bag.w,0.f));

    // phase A: sparse max-aggregation (ballot over batch-member neighbors)
#pragma unroll 1
    for (int p = 0; p < 8; ++p) {
        int n = warp + p * 16;
        int gn = r0 + n;                              // warp-uniform
        float4 acc = make_float4(0.f, 0.f, 0.f, 0.f);
        if (gn < N_NODES) {
            int nb = nbd[gn * DEG + lane];
            int wv = g_winner[nb];
            unsigned mask = __ballot_sync(0xffffffffu, wv >= 0);
            acc = (mask != 0xffffffffu) ? cvec
                  : make_float4(-FLT_MAX, -FLT_MAX, -FLT_MAX, -FLT_MAX);
            while (mask) {
                int j = __ffs(mask) - 1;
                mask &= mask - 1;
                int wj = __shfl_sync(0xffffffffu, wv, j);
                float4 m = *(const float4*)(g_Mb + wj * WID + lane * 4);
                acc.x = fmaxf(acc.x, m.x); acc.y = fmaxf(acc.y, m.y);
                acc.z = fmaxf(acc.z, m.z); acc.w = fmaxf(acc.w, m.w);
            }
        }
        *(float4*)(As + n * AS_LD + lane * 4) = acc;
    }
    load_weights(Wt, g_WlaT);
    __syncthreads();

    // GEMM 1: agg @ Wla^T
    u64 C[2][8];
    zeroC(C);
    gemm128(As, Wt, C, tx, ty);

    // epilogue 1: + b_lin (+ Fh for batch nodes), relu, l2-normalize; stage into As
    float blv[16];
#pragma unroll
    for (int q = 0; q < 4; ++q) {
        float4 b = *(const float4*)(b_lin + tx * 16 + q * 4);
        blv[q*4+0]=b.x; blv[q*4+1]=b.y; blv[q*4+2]=b.z; blv[q*4+3]=b.w;
    }
#pragma unroll
    for (int i = 0; i < 2; ++i) {
        int row = ty * 2 + i, gn = r0 + row;
        float v[16];
#pragma unroll
        for (int j = 0; j < 8; ++j) f2unpack(C[i][j], v[2*j], v[2*j+1]);
#pragma unroll
        for (int c = 0; c < 16; ++c) v[c] += blv[c];
        int w = (gn < N_NODES) ? g_winner[gn] : -1;
        if (w >= 0) {
            const float* fh = g_Fh + w * WID + tx * 16;
#pragma unroll
            for (int q = 0; q < 4; ++q) {
                float4 f = *(const float4*)(fh + q * 4);
                v[q*4+0]+=f.x; v[q*4+1]+=f.y; v[q*4+2]+=f.z; v[q*4+3]+=f.w;
            }
        }
        float s = 0.f;
#pragma unroll
        for (int c = 0; c < 16; ++c) { v[c] = fmaxf(v[c], 0.f); s += v[c]*v[c]; }
        s = rowsum8(s);
        float rinv = 1.0f / fmaxf(sqrtf(s), 1e-12f);
#pragma unroll
        for (int c = 0; c < 16; ++c) v[c] *= rinv;
        // stage normalized H1 row for GEMM2 (row data is intra-warp only)
        float* dst = As + row * AS_LD + tx * 16;
#pragma unroll
        for (int q = 0; q < 4; ++q)
            *(float4*)(dst + q*4) = make_float4(v[q*4], v[q*4+1], v[q*4+2], v[q*4+3]);
        if (w >= 0) {                                  // H1 only consumed at batch nodes
            float* hd = g_H1 + gn * WID + tx * 16;
#pragma unroll
            for (int q = 0; q < 4; ++q)
                *(float4*)(hd + q*4) = make_float4(v[q*4], v[q*4+1], v[q*4+2], v[q*4+3]);
        }
    }
    __syncthreads();
    load_weights(Wt, g_WaT);
    __syncthreads();

    // GEMM 2: M2 = relu(H1 @ Wa^T + ba)
    zeroC(C);
    gemm128(As, Wt, C, tx, ty);

    float bav[16];
#pragma unroll
    for (int q = 0; q < 4; ++q) {
        float4 b = *(const float4*)(b_agg + tx * 16 + q * 4);
        bav[q*4+0]=b.x; bav[q*4+1]=b.y; bav[q*4+2]=b.z; bav[q*4+3]=b.w;
    }
#pragma unroll
    for (int i = 0; i < 2; ++i) {
        int row = ty * 2 + i, gn = r0 + row;
        if (gn >= N_NODES) continue;
        float v[16];
#pragma unroll
        for (int j = 0; j < 8; ++j) f2unpack(C[i][j], v[2*j], v[2*j+1]);
        float* dst = g_M2 + gn * WID + tx * 16;
#pragma unroll
        for (int q = 0; q < 4; ++q)
            *(float4*)(dst + q*4) = make_float4(fmaxf(v[q*4+0]+bav[q*4+0],0.f),
                                                fmaxf(v[q*4+1]+bav[q*4+1],0.f),
                                                fmaxf(v[q*4+2]+bav[q*4+2],0.f),
                                                fmaxf(v[q*4+3]+bav[q*4+3],0.f));
    }
}

// ---------------- layer 2 final: batch agg + 256-K combine + norm ----------------
__global__ void __launch_bounds__(NTHREADS, 1)
k_l2f(const int* __restrict__ nbd, const int* __restrict__ node_idx,
      const float* __restrict__ b_lin, float* __restrict__ out) {
    extern __shared__ float sm[];
    float* A1 = sm;
    float* A2 = A1 + WID * AS_LD;
    float* Wt = A2 + WID * AS_LD;
    int*   nid = (int*)(Wt + WID * WID);
    const int tid = threadIdx.x;
    const int lane = tid & 31, warp = tid >> 5;
    const int tx = tid & 7, ty = tid >> 3;
    const int r0 = blockIdx.x * WID;

    if (tid < WID) nid[tid] = node_idx[r0 + tid];
    __syncthreads();

    for (int e = tid; e < WID * WID / 4; e += NTHREADS) {
        int row = e >> 5, c4 = (e & 31) << 2;
        *(float4*)(A1 + row * AS_LD + c4) = *(const float4*)(g_H1 + nid[row] * WID + c4);
    }
#pragma unroll 1
    for (int p = 0; p < 8; ++p) {
        int n = warp + p * 16;
        int gn = nid[n];                               // warp-uniform shared read
        int nb = nbd[gn * DEG + lane];
        float4 acc = make_float4(-FLT_MAX, -FLT_MAX, -FLT_MAX, -FLT_MAX);
#pragma unroll 1
        for (int j = 0; j < DEG; ++j) {
            int nbj = __shfl_sync(0xffffffffu, nb, j);
            float4 m = *(const float4*)(g_M2 + nbj * WID + lane * 4);
            acc.x = fmaxf(acc.x, m.x); acc.y = fmaxf(acc.y, m.y);
            acc.z = fmaxf(acc.z, m.z); acc.w = fmaxf(acc.w, m.w);
        }
        *(float4*)(A2 + n * AS_LD + lane * 4) = acc;
    }
    load_weights(Wt, g_WlhT);
    __syncthreads();

    u64 C[2][8];
    zeroC(C);
    gemm128(A1, Wt, C, tx, ty);
    __syncthreads();
    load_weights(Wt, g_WlaT);
    __syncthreads();
    gemm128(A2, Wt, C, tx, ty);                        // accumulate second K-half

    float blv[16];
#pragma unroll
    for (int q = 0; q < 4; ++q) {
        float4 b = *(const float4*)(b_lin + tx * 16 + q * 4);
        blv[q*4+0]=b.x; blv[q*4+1]=b.y; blv[q*4+2]=b.z; blv[q*4+3]=b.w;
    }
#pragma unroll
    for (int i = 0; i < 2; ++i) {
        int row = ty * 2 + i;
        float v[16];
#pragma unroll
        for (int j = 0; j < 8; ++j) f2unpack(C[i][j], v[2*j], v[2*j+1]);
        float s = 0.f;
#pragma unroll
        for (int c = 0; c < 16; ++c) { v[c] = fmaxf(v[c] + blv[c], 0.f); s += v[c]*v[c]; }
        s = rowsum8(s);
        float rinv = 1.0f / fmaxf(sqrtf(s), 1e-12f);
        float* dst = out + (r0 + row) * WID + tx * 16;
#pragma unroll
        for (int q = 0; q < 4; ++q)
            *(float4*)(dst + q*4) = make_float4(v[q*4]*rinv, v[q*4+1]*rinv,
                                                v[q*4+2]*rinv, v[q*4+3]*rinv);
    }
}

// ---------------- launch ----------------
extern "C" void kernel_launch(void* const* d_in, const int* in_sizes, int n_in,
                              void* d_out, int out_size) {
    const int*   nbd      = (const int*)d_in[0];
    const int*   node_idx = (const int*)d_in[1];
    const float* feats    = (const float*)d_in[2];
    const float* W_agg    = (const float*)d_in[3];
    const float* b_agg    = (const float*)d_in[4];
    const float* W_lin    = (const float*)d_in[5];
    const float* b_lin    = (const float*)d_in[6];
    float* out = (float*)d_out;

    const int smAW  = (WID * AS_LD + WID * WID) * (int)sizeof(float);     // 133120
    const int smL2F = (2 * WID * AS_LD + WID * WID) * (int)sizeof(float)
                      + WID * (int)sizeof(int);                            // 201216

    cudaFuncSetAttribute(k_batch, cudaFuncAttributeMaxDynamicSharedMemorySize, smAW);
    cudaFuncSetAttribute(k_main,  cudaFuncAttributeMaxDynamicSharedMemorySize, smAW);
    cudaFuncSetAttribute(k_l2f,   cudaFuncAttributeMaxDynamicSharedMemorySize, smL2F);

    k_init<<<(N_NODES + NTHREADS - 1) / NTHREADS, NTHREADS>>>(W_agg, W_lin);
    k_scatter<<<BATCH / NTHREADS, NTHREADS>>>(node_idx);
    k_batch<<<BATCH / WID, NTHREADS, smAW>>>(feats, b_agg);
    k_main<<<(N_NODES + WID - 1) / WID, NTHREADS, smAW>>>(nbd, b_agg, b_lin);
    k_l2f<<<BATCH / WID, NTHREADS, smL2F>>>(nbd, node_idx, b_lin, out);
}

// round 3
// speedup vs baseline: 3.0148x; 3.0148x over previous
#include <cuda_runtime.h>
#include <float.h>

#define N_NODES 50000
#define DEG     32
#define WID     128
#define BATCH   4096
#define AS_LDT  130          // transposed tile leading dim (even, for LDS.64 alignment)
#define NT      512

// ---------------- device scratch ----------------
__device__ int   g_winner[N_NODES];
__device__ float g_Mb[BATCH * WID];     // relu(feats @ Wa^T + ba)
__device__ float g_Fh[BATCH * WID];     // feats @ Wlh^T
__device__ float g_H1[N_NODES * WID];   // layer-1 output (batch rows only consumed)
__device__ float g_M2[N_NODES * WID];   // relu(H1 @ Wa^T + ba)
__device__ float g_WaT[WID * WID];      // k-major: Wt[k][d]
__device__ float g_WlhT[WID * WID];
__device__ float g_WlaT[WID * WID];

typedef unsigned long long u64;

__device__ __forceinline__ u64 f2pack(float lo, float hi) {
    u64 r; asm("mov.b64 %0, {%1, %2};" : "=l"(r) : "f"(lo), "f"(hi)); return r;
}
__device__ __forceinline__ void f2unpack(u64 v, float& lo, float& hi) {
    asm("mov.b64 {%0, %1}, %2;" : "=f"(lo), "=f"(hi) : "l"(v));
}
__device__ __forceinline__ void f2fma(u64& c, u64 a, u64 b) {
    asm("fma.rn.f32x2 %0, %1, %2, %0;" : "+l"(c) : "l"(a), "l"(b));
}

// ---------------- conflict-free 128x128x128 tile GEMM ----------------
// As: TRANSPOSED [k][row], ld AS_LDT.  Wt: [k][d], ld WID.
// 512 threads, 16 warps. warp: cg = w>>1 (16-col group), rowblock = (w&1)*64.
// thread: rows rowb, rowb+1 (rowb = rowblock + lane*2); cols cg*16..+15.
// B loads warp-uniform (broadcast), A loads contiguous LDS.64.
__device__ __forceinline__ void gemmT(const float* __restrict__ As,
                                      const float* __restrict__ Wt,
                                      u64 C[2][8], int rowb, int cg) {
    const float* ap = As + rowb;
    const float* bp = Wt + cg * 16;
#pragma unroll 4
    for (int k = 0; k < WID; ++k) {
        float2 av = *(const float2*)(ap + k * AS_LDT);
        const ulonglong2* b = (const ulonglong2*)(bp + k * WID);
        ulonglong2 q0 = b[0], q1 = b[1], q2 = b[2], q3 = b[3];
        u64 bb[8] = { q0.x, q0.y, q1.x, q1.y, q2.x, q2.y, q3.x, q3.y };
        u64 a0 = f2pack(av.x, av.x), a1 = f2pack(av.y, av.y);
#pragma unroll
        for (int j = 0; j < 8; ++j) { f2fma(C[0][j], a0, bb[j]); f2fma(C[1][j], a1, bb[j]); }
    }
}

__device__ __forceinline__ void zeroC(u64 C[2][8]) {
#pragma unroll
    for (int i = 0; i < 2; ++i)
#pragma unroll
        for (int j = 0; j < 8; ++j) C[i][j] = 0ull;
}

__device__ __forceinline__ void load_weights(float* Wt, const float* __restrict__ src) {
    for (int e = threadIdx.x; e < WID * WID / 4; e += NT)
        *(float4*)(Wt + e * 4) = *(const float4*)(src + e * 4);
}

__device__ __forceinline__ void unpackrow(const u64* Cr, float* v) {
#pragma unroll
    for (int j = 0; j < 8; ++j) f2unpack(Cr[j], v[2 * j], v[2 * j + 1]);
}

__device__ __forceinline__ void loadbias16(const float* __restrict__ b, int cg, float* bv) {
#pragma unroll
    for (int q = 0; q < 4; ++q) {
        float4 t = *(const float4*)(b + cg * 16 + q * 4);
        bv[q * 4 + 0] = t.x; bv[q * 4 + 1] = t.y; bv[q * 4 + 2] = t.z; bv[q * 4 + 3] = t.w;
    }
}

// ---------------- setup ----------------
__global__ void k_init(const float* __restrict__ W_agg, const float* __restrict__ W_lin) {
    int t = blockIdx.x * NT + threadIdx.x;
    if (t < N_NODES) g_winner[t] = -1;
    if (t < WID * WID) {
        int k = t >> 7, d = t & 127;
        g_WaT[t]  = W_agg[d * WID + k];
        g_WlhT[t] = W_lin[d * (2 * WID) + k];
        g_WlaT[t] = W_lin[d * (2 * WID) + WID + k];
    }
}

__global__ void k_scatter(const int* __restrict__ node_idx) {
    int i = blockIdx.x * NT + threadIdx.x;
    if (i < BATCH) atomicMax(&g_winner[node_idx[i]], i);
}

// ---------------- batch precompute: Mb and Fh ----------------
__global__ void __launch_bounds__(NT, 1)
k_batch(const float* __restrict__ feats, const float* __restrict__ b_agg) {
    extern __shared__ float sm[];
    float* As = sm;                         // [k][row] transposed
    float* Wt = As + WID * AS_LDT;
    const int tid = threadIdx.x, lane = tid & 31, warp = tid >> 5;
    const int cg = warp >> 1, rowb = (warp & 1) * 64 + lane * 2;
    const int r0 = blockIdx.x * WID;

    // stage feats transposed
    for (int e = tid; e < WID * 32; e += NT) {
        int row = e >> 5, c4 = (e & 31) << 2;
        float4 f = *(const float4*)(feats + (r0 + row) * WID + c4);
        As[(c4 + 0) * AS_LDT + row] = f.x;
        As[(c4 + 1) * AS_LDT + row] = f.y;
        As[(c4 + 2) * AS_LDT + row] = f.z;
        As[(c4 + 3) * AS_LDT + row] = f.w;
    }
    load_weights(Wt, g_WaT);
    __syncthreads();

    u64 C[2][8];
    zeroC(C);
    gemmT(As, Wt, C, rowb, cg);

    float bav[16];
    loadbias16(b_agg, cg, bav);
#pragma unroll
    for (int i = 0; i < 2; ++i) {
        float v[16];
        unpackrow(C[i], v);
        float* dst = g_Mb + (r0 + rowb + i) * WID + cg * 16;
#pragma unroll
        for (int q = 0; q < 4; ++q)
            *(float4*)(dst + q * 4) = make_float4(fmaxf(v[q*4+0]+bav[q*4+0],0.f),
                                                  fmaxf(v[q*4+1]+bav[q*4+1],0.f),
                                                  fmaxf(v[q*4+2]+bav[q*4+2],0.f),
                                                  fmaxf(v[q*4+3]+bav[q*4+3],0.f));
    }
    __syncthreads();
    load_weights(Wt, g_WlhT);
    __syncthreads();

    zeroC(C);
    gemmT(As, Wt, C, rowb, cg);
#pragma unroll
    for (int i = 0; i < 2; ++i) {
        float v[16];
        unpackrow(C[i], v);
        float* dst = g_Fh + (r0 + rowb + i) * WID + cg * 16;
#pragma unroll
        for (int q = 0; q < 4; ++q)
            *(float4*)(dst + q * 4) = make_float4(v[q*4], v[q*4+1], v[q*4+2], v[q*4+3]);
    }
}

// ---------------- main fused: layer1 (agg+combine+norm) + layer2 M2 ----------------
__global__ void __launch_bounds__(NT, 1)
k_main(const int* __restrict__ nbd, const float* __restrict__ b_agg,
       const float* __restrict__ b_lin) {
    extern __shared__ float sm[];
    float* As = sm;                          // [k][row] transposed
    float* Wt = As + WID * AS_LDT;
    float* ps = Wt + WID * WID;              // [8][128] norm partials
    const int tid = threadIdx.x, lane = tid & 31, warp = tid >> 5;
    const int cg = warp >> 1, rowb = (warp & 1) * 64 + lane * 2;
    const int r0 = blockIdx.x * WID;

    float4 bag = *(const float4*)(b_agg + lane * 4);
    float4 cvec = make_float4(fmaxf(bag.x,0.f), fmaxf(bag.y,0.f),
                              fmaxf(bag.z,0.f), fmaxf(bag.w,0.f));

    // phase A: sparse max-aggregation, written TRANSPOSED into As
#pragma unroll 1
    for (int p = 0; p < 8; ++p) {
        int n = warp + p * 16;
        int gn = r0 + n;                     // warp-uniform
        float4 acc = make_float4(0.f, 0.f, 0.f, 0.f);
        if (gn < N_NODES) {
            int nb = nbd[gn * DEG + lane];
            int wv = g_winner[nb];
            unsigned mask = __ballot_sync(0xffffffffu, wv >= 0);
            acc = (mask != 0xffffffffu) ? cvec
                  : make_float4(-FLT_MAX, -FLT_MAX, -FLT_MAX, -FLT_MAX);
            while (mask) {
                int j = __ffs(mask) - 1;
                mask &= mask - 1;
                int wj = __shfl_sync(0xffffffffu, wv, j);
                float4 m = *(const float4*)(g_Mb + wj * WID + lane * 4);
                acc.x = fmaxf(acc.x, m.x); acc.y = fmaxf(acc.y, m.y);
                acc.z = fmaxf(acc.z, m.z); acc.w = fmaxf(acc.w, m.w);
            }
        }
        As[(lane * 4 + 0) * AS_LDT + n] = acc.x;
        As[(lane * 4 + 1) * AS_LDT + n] = acc.y;
        As[(lane * 4 + 2) * AS_LDT + n] = acc.z;
        As[(lane * 4 + 3) * AS_LDT + n] = acc.w;
    }
    load_weights(Wt, g_WlaT);
    __syncthreads();

    // GEMM 1: agg @ Wla^T
    u64 C[2][8];
    zeroC(C);
    gemmT(As, Wt, C, rowb, cg);

    // epilogue 1: + b_lin (+Fh for batch rows), relu, l2-normalize
    float blv[16];
    loadbias16(b_lin, cg, blv);
    float v0[16], v1[16];
    unpackrow(C[0], v0);
    unpackrow(C[1], v1);
    const int gn0 = r0 + rowb, gn1 = gn0 + 1;
    const int w0 = (gn0 < N_NODES) ? g_winner[gn0] : -1;
    const int w1 = (gn1 < N_NODES) ? g_winner[gn1] : -1;
#pragma unroll
    for (int c = 0; c < 16; ++c) { v0[c] += blv[c]; v1[c] += blv[c]; }
    if (w0 >= 0) {
        const float* fh = g_Fh + w0 * WID + cg * 16;
#pragma unroll
        for (int q = 0; q < 4; ++q) {
            float4 f = *(const float4*)(fh + q * 4);
            v0[q*4+0]+=f.x; v0[q*4+1]+=f.y; v0[q*4+2]+=f.z; v0[q*4+3]+=f.w;
        }
    }
    if (w1 >= 0) {
        const float* fh = g_Fh + w1 * WID + cg * 16;
#pragma unroll
        for (int q = 0; q < 4; ++q) {
            float4 f = *(const float4*)(fh + q * 4);
            v1[q*4+0]+=f.x; v1[q*4+1]+=f.y; v1[q*4+2]+=f.z; v1[q*4+3]+=f.w;
        }
    }
    float s0 = 0.f, s1 = 0.f;
#pragma unroll
    for (int c = 0; c < 16; ++c) {
        v0[c] = fmaxf(v0[c], 0.f); s0 += v0[c] * v0[c];
        v1[c] = fmaxf(v1[c], 0.f); s1 += v1[c] * v1[c];
    }
    ps[cg * WID + rowb]     = s0;
    ps[cg * WID + rowb + 1] = s1;
    __syncthreads();                         // also closes GEMM1's Wt/As reads
    float t0 = 0.f, t1 = 0.f;
#pragma unroll
    for (int g = 0; g < 8; ++g) { t0 += ps[g * WID + rowb]; t1 += ps[g * WID + rowb + 1]; }
    const float rinv0 = 1.0f / fmaxf(sqrtf(t0), 1e-12f);
    const float rinv1 = 1.0f / fmaxf(sqrtf(t1), 1e-12f);
#pragma unroll
    for (int c = 0; c < 16; ++c) { v0[c] *= rinv0; v1[c] *= rinv1; }

    // stage normalized H1 transposed into As (for GEMM2); write H1 global for batch rows
#pragma unroll
    for (int c = 0; c < 16; ++c)
        *(float2*)(As + (cg * 16 + c) * AS_LDT + rowb) = make_float2(v0[c], v1[c]);
    if (w0 >= 0) {
        float* hd = g_H1 + gn0 * WID + cg * 16;
#pragma unroll
        for (int q = 0; q < 4; ++q)
            *(float4*)(hd + q*4) = make_float4(v0[q*4], v0[q*4+1], v0[q*4+2], v0[q*4+3]);
    }
    if (w1 >= 0) {
        float* hd = g_H1 + gn1 * WID + cg * 16;
#pragma unroll
        for (int q = 0; q < 4; ++q)
            *(float4*)(hd + q*4) = make_float4(v1[q*4], v1[q*4+1], v1[q*4+2], v1[q*4+3]);
    }
    load_weights(Wt, g_WaT);
    __syncthreads();

    // GEMM 2: M2 = relu(H1 @ Wa^T + ba)
    zeroC(C);
    gemmT(As, Wt, C, rowb, cg);

    float bav[16];
    loadbias16(b_agg, cg, bav);
#pragma unroll
    for (int i = 0; i < 2; ++i) {
        int gn = r0 + rowb + i;
        if (gn >= N_NODES) continue;
        float v[16];
        unpackrow(C[i], v);
        float* dst = g_M2 + gn * WID + cg * 16;
#pragma unroll
        for (int q = 0; q < 4; ++q)
            *(float4*)(dst + q * 4) = make_float4(fmaxf(v[q*4+0]+bav[q*4+0],0.f),
                                                  fmaxf(v[q*4+1]+bav[q*4+1],0.f),
                                                  fmaxf(v[q*4+2]+bav[q*4+2],0.f),
                                                  fmaxf(v[q*4+3]+bav[q*4+3],0.f));
    }
}

// ---------------- layer 2 final: batch agg + 256-K combine + norm ----------------
__global__ void __launch_bounds__(NT, 1)
k_l2f(const int* __restrict__ nbd, const int* __restrict__ node_idx,
      const float* __restrict__ b_lin, float* __restrict__ out) {
    extern __shared__ float sm[];
    float* A1 = sm;                          // H1 rows of batch nodes, transposed
    float* A2 = A1 + WID * AS_LDT;           // agg2, transposed
    float* Wt = A2 + WID * AS_LDT;
    float* ps = Wt + WID * WID;
    int*   nid = (int*)(ps + 8 * WID);
    const int tid = threadIdx.x, lane = tid & 31, warp = tid >> 5;
    const int cg = warp >> 1, rowb = (warp & 1) * 64 + lane * 2;
    const int r0 = blockIdx.x * WID;

    if (tid < WID) nid[tid] = node_idx[r0 + tid];
    __syncthreads();

    for (int e = tid; e < WID * 32; e += NT) {
        int row = e >> 5, c4 = (e & 31) << 2;
        float4 f = *(const float4*)(g_H1 + nid[row] * WID + c4);
        A1[(c4 + 0) * AS_LDT + row] = f.x;
        A1[(c4 + 1) * AS_LDT + row] = f.y;
        A1[(c4 + 2) * AS_LDT + row] = f.z;
        A1[(c4 + 3) * AS_LDT + row] = f.w;
    }
#pragma unroll 1
    for (int p = 0; p < 8; ++p) {
        int n = warp + p * 16;
        int gn = nid[n];                     // warp-uniform shared read
        int nb = nbd[gn * DEG + lane];
        float4 acc = make_float4(-FLT_MAX, -FLT_MAX, -FLT_MAX, -FLT_MAX);
#pragma unroll 1
        for (int j = 0; j < DEG; ++j) {
            int nbj = __shfl_sync(0xffffffffu, nb, j);
            float4 m = *(const float4*)(g_M2 + nbj * WID + lane * 4);
            acc.x = fmaxf(acc.x, m.x); acc.y = fmaxf(acc.y, m.y);
            acc.z = fmaxf(acc.z, m.z); acc.w = fmaxf(acc.w, m.w);
        }
        A2[(lane * 4 + 0) * AS_LDT + n] = acc.x;
        A2[(lane * 4 + 1) * AS_LDT + n] = acc.y;
        A2[(lane * 4 + 2) * AS_LDT + n] = acc.z;
        A2[(lane * 4 + 3) * AS_LDT + n] = acc.w;
    }
    load_weights(Wt, g_WlhT);
    __syncthreads();

    u64 C[2][8];
    zeroC(C);
    gemmT(A1, Wt, C, rowb, cg);
    __syncthreads();
    load_weights(Wt, g_WlaT);
    __syncthreads();
    gemmT(A2, Wt, C, rowb, cg);              // accumulate second K-half

    float blv[16];
    loadbias16(b_lin, cg, blv);
    float v0[16], v1[16];
    unpackrow(C[0], v0);
    unpackrow(C[1], v1);
    float s0 = 0.f, s1 = 0.f;
#pragma unroll
    for (int c = 0; c < 16; ++c) {
        v0[c] = fmaxf(v0[c] + blv[c], 0.f); s0 += v0[c] * v0[c];
        v1[c] = fmaxf(v1[c] + blv[c], 0.f); s1 += v1[c] * v1[c];
    }
    ps[cg * WID + rowb]     = s0;
    ps[cg * WID + rowb + 1] = s1;
    __syncthreads();
    float t0 = 0.f, t1 = 0.f;
#pragma unroll
    for (int g = 0; g < 8; ++g) { t0 += ps[g * WID + rowb]; t1 += ps[g * WID + rowb + 1]; }
    const float rinv0 = 1.0f / fmaxf(sqrtf(t0), 1e-12f);
    const float rinv1 = 1.0f / fmaxf(sqrtf(t1), 1e-12f);
    float* d0 = out + (r0 + rowb) * WID + cg * 16;
    float* d1 = out + (r0 + rowb + 1) * WID + cg * 16;
#pragma unroll
    for (int q = 0; q < 4; ++q) {
        *(float4*)(d0 + q*4) = make_float4(v0[q*4]*rinv0, v0[q*4+1]*rinv0,
                                           v0[q*4+2]*rinv0, v0[q*4+3]*rinv0);
        *(float4*)(d1 + q*4) = make_float4(v1[q*4]*rinv1, v1[q*4+1]*rinv1,
                                           v1[q*4+2]*rinv1, v1[q*4+3]*rinv1);
    }
}

// ---------------- launch ----------------
extern "C" void kernel_launch(void* const* d_in, const int* in_sizes, int n_in,
                              void* d_out, int out_size) {
    const int*   nbd      = (const int*)d_in[0];
    const int*   node_idx = (const int*)d_in[1];
    const float* feats    = (const float*)d_in[2];
    const float* W_agg    = (const float*)d_in[3];
    const float* b_agg    = (const float*)d_in[4];
    const float* W_lin    = (const float*)d_in[5];
    const float* b_lin    = (const float*)d_in[6];
    float* out = (float*)d_out;

    const int smB  = (WID * AS_LDT + WID * WID) * (int)sizeof(float);              // 132096
    const int smM  = (WID * AS_LDT + WID * WID + 8 * WID) * (int)sizeof(float);    // 136192
    const int smF  = (2 * WID * AS_LDT + WID * WID + 8 * WID) * (int)sizeof(float)
                     + WID * (int)sizeof(int);                                     // 203264

    cudaFuncSetAttribute(k_batch, cudaFuncAttributeMaxDynamicSharedMemorySize, smB);
    cudaFuncSetAttribute(k_main,  cudaFuncAttributeMaxDynamicSharedMemorySize, smM);
    cudaFuncSetAttribute(k_l2f,   cudaFuncAttributeMaxDynamicSharedMemorySize, smF);

    k_init<<<(N_NODES + NT - 1) / NT, NT>>>(W_agg, W_lin);
    k_scatter<<<BATCH / NT, NT>>>(node_idx);
    k_batch<<<BATCH / WID, NT, smB>>>(feats, b_agg);
    k_main<<<(N_NODES + WID - 1) / WID, NT, smM>>>(nbd, b_agg, b_lin);
    k_l2f<<<BATCH / WID, NT, smF>>>(nbd, node_idx, b_lin, out);
}

// round 5
// speedup vs baseline: 3.3636x; 1.1157x over previous
#include <cuda_runtime.h>
#include <float.h>

#define N_NODES 50000
#define DEG     32
#define WID     128
#define BATCH   4096
#define TM      64           // tile rows per CTA
#define AS_LDT  66           // transposed tile ld (even for LDS.64 alignment)
#define NT      256

// ---------------- device scratch ----------------
__device__ int   g_winner[N_NODES];
__device__ float g_Mb[BATCH * WID];     // relu(feats @ Wa^T + ba)
__device__ float g_Fh[BATCH * WID];     // feats @ Wlh^T
__device__ float g_H1[N_NODES * WID];   // layer-1 output (batch rows only consumed)
__device__ float g_M2[N_NODES * WID];   // relu(H1 @ Wa^T + ba)
__device__ float g_A2[BATCH * WID];     // layer-2 aggregate per batch slot
__device__ float g_WaT[WID * WID];      // k-major: W[k][d]
__device__ float g_WlhT[WID * WID];
__device__ float g_WlaT[WID * WID];

typedef unsigned long long u64;

__device__ __forceinline__ u64 f2pack(float lo, float hi) {
    u64 r; asm("mov.b64 %0, {%1, %2};" : "=l"(r) : "f"(lo), "f"(hi)); return r;
}
__device__ __forceinline__ void f2unpack(u64 v, float& lo, float& hi) {
    asm("mov.b64 {%0, %1}, %2;" : "=f"(lo), "=f"(hi) : "l"(v));
}
__device__ __forceinline__ void f2fma(u64& c, u64 a, u64 b) {
    asm("fma.rn.f32x2 %0, %1, %2, %0;" : "+l"(c) : "l"(a), "l"(b));
}

// ---------------- conflict-free 64x128x128 tile GEMM ----------------
// As: TRANSPOSED [k][row], ld AS_LDT (64 rows). W: GLOBAL k-major [k][128].
// 256 threads, 8 warps. warp = cg (16-col group). thread: rows lane*2, lane*2+1.
// B loads: warp-uniform LDG.128 (L1 broadcast). A loads: contiguous LDS.64.
__device__ __forceinline__ void gemmT(const float* __restrict__ As,
                                      const float* __restrict__ gW,
                                      u64 C[2][8], int rowb, int cg) {
    const float* ap = As + rowb;
    const ulonglong2* bp = (const ulonglong2*)(gW + cg * 16);  // +k*32 per k row
#pragma unroll 4
    for (int k = 0; k < WID; ++k) {
        float2 av = *(const float2*)(ap + k * AS_LDT);
        ulonglong2 q0 = __ldg(bp + k * 32 + 0);
        ulonglong2 q1 = __ldg(bp + k * 32 + 1);
        ulonglong2 q2 = __ldg(bp + k * 32 + 2);
        ulonglong2 q3 = __ldg(bp + k * 32 + 3);
        u64 bb[8] = { q0.x, q0.y, q1.x, q1.y, q2.x, q2.y, q3.x, q3.y };
        u64 a0 = f2pack(av.x, av.x), a1 = f2pack(av.y, av.y);
#pragma unroll
        for (int j = 0; j < 8; ++j) { f2fma(C[0][j], a0, bb[j]); f2fma(C[1][j], a1, bb[j]); }
    }
}

__device__ __forceinline__ void zeroC(u64 C[2][8]) {
#pragma unroll
    for (int i = 0; i < 2; ++i)
#pragma unroll
        for (int j = 0; j < 8; ++j) C[i][j] = 0ull;
}

__device__ __forceinline__ void unpackrow(const u64* Cr, float* v) {
#pragma unroll
    for (int j = 0; j < 8; ++j) f2unpack(Cr[j], v[2 * j], v[2 * j + 1]);
}

__device__ __forceinline__ void loadbias16(const float* __restrict__ b, int cg, float* bv) {
#pragma unroll
    for (int q = 0; q < 4; ++q) {
        float4 t = *(const float4*)(b + cg * 16 + q * 4);
        bv[q*4+0] = t.x; bv[q*4+1] = t.y; bv[q*4+2] = t.z; bv[q*4+3] = t.w;
    }
}

// ---------------- setup ----------------
__global__ void k_init(const float* __restrict__ W_agg, const float* __restrict__ W_lin) {
    int t = blockIdx.x * NT + threadIdx.x;
    if (t < N_NODES) g_winner[t] = -1;
    if (t < WID * WID) {
        int k = t >> 7, d = t & 127;
        g_WaT[t]  = W_agg[d * WID + k];
        g_WlhT[t] = W_lin[d * (2 * WID) + k];
        g_WlaT[t] = W_lin[d * (2 * WID) + WID + k];
    }
}

__global__ void k_scatter(const int* __restrict__ node_idx) {
    int i = blockIdx.x * NT + threadIdx.x;
    if (i < BATCH) atomicMax(&g_winner[node_idx[i]], i);
}

// ---------------- batch precompute: Mb and Fh ----------------
__global__ void __launch_bounds__(NT, 3)
k_batch(const float* __restrict__ feats, const float* __restrict__ b_agg) {
    __shared__ float As[WID * AS_LDT];
    const int tid = threadIdx.x, lane = tid & 31, cg = tid >> 5;
    const int rowb = lane * 2;
    const int r0 = blockIdx.x * TM;

    for (int e = tid; e < TM * 32; e += NT) {
        int row = e >> 5, c4 = (e & 31) << 2;
        float4 f = *(const float4*)(feats + (r0 + row) * WID + c4);
        As[(c4 + 0) * AS_LDT + row] = f.x;
        As[(c4 + 1) * AS_LDT + row] = f.y;
        As[(c4 + 2) * AS_LDT + row] = f.z;
        As[(c4 + 3) * AS_LDT + row] = f.w;
    }
    __syncthreads();

    u64 C[2][8];
    zeroC(C);
    gemmT(As, g_WaT, C, rowb, cg);

    float bav[16];
    loadbias16(b_agg, cg, bav);
#pragma unroll
    for (int i = 0; i < 2; ++i) {
        float v[16];
        unpackrow(C[i], v);
        float* dst = g_Mb + (r0 + rowb + i) * WID + cg * 16;
#pragma unroll
        for (int q = 0; q < 4; ++q)
            *(float4*)(dst + q*4) = make_float4(fmaxf(v[q*4+0]+bav[q*4+0],0.f),
                                                fmaxf(v[q*4+1]+bav[q*4+1],0.f),
                                                fmaxf(v[q*4+2]+bav[q*4+2],0.f),
                                                fmaxf(v[q*4+3]+bav[q*4+3],0.f));
    }

    zeroC(C);
    gemmT(As, g_WlhT, C, rowb, cg);
#pragma unroll
    for (int i = 0; i < 2; ++i) {
        float v[16];
        unpackrow(C[i], v);
        float* dst = g_Fh + (r0 + rowb + i) * WID + cg * 16;
#pragma unroll
        for (int q = 0; q < 4; ++q)
            *(float4*)(dst + q*4) = make_float4(v[q*4], v[q*4+1], v[q*4+2], v[q*4+3]);
    }
}

// ---------------- main fused: layer1 (agg+combine+norm) + layer2 M2 ----------------
__global__ void __launch_bounds__(NT, 3)
k_main(const int* __restrict__ nbd, const float* __restrict__ b_agg,
       const float* __restrict__ b_lin) {
    __shared__ float As[WID * AS_LDT];
    __shared__ float ps[8 * TM];
    const int tid = threadIdx.x, lane = tid & 31, warp = tid >> 5;
    const int cg = warp, rowb = lane * 2;
    const int r0 = blockIdx.x * TM;

    float4 bag = *(const float4*)(b_agg + lane * 4);
    float4 cvec = make_float4(fmaxf(bag.x,0.f), fmaxf(bag.y,0.f),
                              fmaxf(bag.z,0.f), fmaxf(bag.w,0.f));

    // phase A: sparse max-aggregation, written TRANSPOSED into As
#pragma unroll 1
    for (int p = 0; p < 8; ++p) {
        int n = p * 8 + warp;
        int gn = r0 + n;                     // warp-uniform
        float4 acc = make_float4(0.f, 0.f, 0.f, 0.f);
        if (gn < N_NODES) {
            int nb = nbd[gn * DEG + lane];
            int wv = g_winner[nb];
            unsigned mask = __ballot_sync(0xffffffffu, wv >= 0);
            acc = (mask != 0xffffffffu) ? cvec
                  : make_float4(-FLT_MAX, -FLT_MAX, -FLT_MAX, -FLT_MAX);
            while (mask) {
                int j = __ffs(mask) - 1;
                mask &= mask - 1;
                int wj = __shfl_sync(0xffffffffu, wv, j);
                float4 m = *(const float4*)(g_Mb + wj * WID + lane * 4);
                acc.x = fmaxf(acc.x, m.x); acc.y = fmaxf(acc.y, m.y);
                acc.z = fmaxf(acc.z, m.z); acc.w = fmaxf(acc.w, m.w);
            }
        }
        As[(lane * 4 + 0) * AS_LDT + n] = acc.x;
        As[(lane * 4 + 1) * AS_LDT + n] = acc.y;
        As[(lane * 4 + 2) * AS_LDT + n] = acc.z;
        As[(lane * 4 + 3) * AS_LDT + n] = acc.w;
    }
    __syncthreads();

    // GEMM 1: agg @ Wla^T
    u64 C[2][8];
    zeroC(C);
    gemmT(As, g_WlaT, C, rowb, cg);

    // epilogue 1: + b_lin (+Fh for batch rows), relu, l2-normalize
    float blv[16];
    loadbias16(b_lin, cg, blv);
    float v0[16], v1[16];
    unpackrow(C[0], v0);
    unpackrow(C[1], v1);
    const int gn0 = r0 + rowb, gn1 = gn0 + 1;
    const int w0 = (gn0 < N_NODES) ? g_winner[gn0] : -1;
    const int w1 = (gn1 < N_NODES) ? g_winner[gn1] : -1;
#pragma unroll
    for (int c = 0; c < 16; ++c) { v0[c] += blv[c]; v1[c] += blv[c]; }
    if (w0 >= 0) {
        const float* fh = g_Fh + w0 * WID + cg * 16;
#pragma unroll
        for (int q = 0; q < 4; ++q) {
            float4 f = *(const float4*)(fh + q * 4);
            v0[q*4+0]+=f.x; v0[q*4+1]+=f.y; v0[q*4+2]+=f.z; v0[q*4+3]+=f.w;
        }
    }
    if (w1 >= 0) {
        const float* fh = g_Fh + w1 * WID + cg * 16;
#pragma unroll
        for (int q = 0; q < 4; ++q) {
            float4 f = *(const float4*)(fh + q * 4);
            v1[q*4+0]+=f.x; v1[q*4+1]+=f.y; v1[q*4+2]+=f.z; v1[q*4+3]+=f.w;
        }
    }
    float s0 = 0.f, s1 = 0.f;
#pragma unroll
    for (int c = 0; c < 16; ++c) {
        v0[c] = fmaxf(v0[c], 0.f); s0 += v0[c] * v0[c];
        v1[c] = fmaxf(v1[c], 0.f); s1 += v1[c] * v1[c];
    }
    ps[cg * TM + rowb]     = s0;
    ps[cg * TM + rowb + 1] = s1;
    __syncthreads();                         // closes GEMM1's As reads too
    float t0 = 0.f, t1 = 0.f;
#pragma unroll
    for (int g = 0; g < 8; ++g) { t0 += ps[g * TM + rowb]; t1 += ps[g * TM + rowb + 1]; }
    const float rinv0 = 1.0f / fmaxf(sqrtf(t0), 1e-12f);
    const float rinv1 = 1.0f / fmaxf(sqrtf(t1), 1e-12f);
#pragma unroll
    for (int c = 0; c < 16; ++c) { v0[c] *= rinv0; v1[c] *= rinv1; }

    // stage normalized H1 transposed; write H1 global for batch rows
#pragma unroll
    for (int c = 0; c < 16; ++c)
        *(float2*)(As + (cg * 16 + c) * AS_LDT + rowb) = make_float2(v0[c], v1[c]);
    if (w0 >= 0) {
        float* hd = g_H1 + gn0 * WID + cg * 16;
#pragma unroll
        for (int q = 0; q < 4; ++q)
            *(float4*)(hd + q*4) = make_float4(v0[q*4], v0[q*4+1], v0[q*4+2], v0[q*4+3]);
    }
    if (w1 >= 0) {
        float* hd = g_H1 + gn1 * WID + cg * 16;
#pragma unroll
        for (int q = 0; q < 4; ++q)
            *(float4*)(hd + q*4) = make_float4(v1[q*4], v1[q*4+1], v1[q*4+2], v1[q*4+3]);
    }
    __syncthreads();

    // GEMM 2: M2 = relu(H1 @ Wa^T + ba)
    zeroC(C);
    gemmT(As, g_WaT, C, rowb, cg);

    float bav[16];
    loadbias16(b_agg, cg, bav);
#pragma unroll
    for (int i = 0; i < 2; ++i) {
        int gn = r0 + rowb + i;
        if (gn >= N_NODES) continue;
        float v[16];
        unpackrow(C[i], v);
        float* dst = g_M2 + gn * WID + cg * 16;
#pragma unroll
        for (int q = 0; q < 4; ++q)
            *(float4*)(dst + q*4) = make_float4(fmaxf(v[q*4+0]+bav[q*4+0],0.f),
                                                fmaxf(v[q*4+1]+bav[q*4+1],0.f),
                                                fmaxf(v[q*4+2]+bav[q*4+2],0.f),
                                                fmaxf(v[q*4+3]+bav[q*4+3],0.f));
    }
}

// ---------------- layer-2 aggregation spread across the chip ----------------
__global__ void __launch_bounds__(NT, 4)
k_agg2(const int* __restrict__ nbd, const int* __restrict__ node_idx) {
    const int lane = threadIdx.x & 31, warp = threadIdx.x >> 5;
    const int slot = blockIdx.x * 8 + warp;          // batch slot
    const int gn = node_idx[slot];                   // warp-uniform
    int nb = nbd[gn * DEG + lane];
    float4 acc = make_float4(-FLT_MAX, -FLT_MAX, -FLT_MAX, -FLT_MAX);
#pragma unroll 1
    for (int j = 0; j < DEG; ++j) {
        int nbj = __shfl_sync(0xffffffffu, nb, j);
        float4 m = *(const float4*)(g_M2 + nbj * WID + lane * 4);
        acc.x = fmaxf(acc.x, m.x); acc.y = fmaxf(acc.y, m.y);
        acc.z = fmaxf(acc.z, m.z); acc.w = fmaxf(acc.w, m.w);
    }
    *(float4*)(g_A2 + slot * WID + lane * 4) = acc;
}

// ---------------- layer 2 final: 256-K combine + norm (dynamic smem) ----------------
#define L2F_SMEM ((2 * WID * AS_LDT + 8 * TM) * (int)sizeof(float) + TM * (int)sizeof(int))
__global__ void __launch_bounds__(NT, 1)
k_l2f(const int* __restrict__ node_idx, const float* __restrict__ b_lin,
      float* __restrict__ out) {
    extern __shared__ float smdyn[];
    float* A1 = smdyn;
    float* A2 = A1 + WID * AS_LDT;
    float* ps = A2 + WID * AS_LDT;
    int*   nid = (int*)(ps + 8 * TM);
    const int tid = threadIdx.x, lane = tid & 31, warp = tid >> 5;
    const int cg = warp, rowb = lane * 2;
    const int r0 = blockIdx.x * TM;

    if (tid < TM) nid[tid] = node_idx[r0 + tid];
    __syncthreads();

    for (int e = tid; e < TM * 32; e += NT) {
        int row = e >> 5, c4 = (e & 31) << 2;
        float4 f = *(const float4*)(g_H1 + nid[row] * WID + c4);
        A1[(c4 + 0) * AS_LDT + row] = f.x;
        A1[(c4 + 1) * AS_LDT + row] = f.y;
        A1[(c4 + 2) * AS_LDT + row] = f.z;
        A1[(c4 + 3) * AS_LDT + row] = f.w;
        float4 g = *(const float4*)(g_A2 + (r0 + row) * WID + c4);
        A2[(c4 + 0) * AS_LDT + row] = g.x;
        A2[(c4 + 1) * AS_LDT + row] = g.y;
        A2[(c4 + 2) * AS_LDT + row] = g.z;
        A2[(c4 + 3) * AS_LDT + row] = g.w;
    }
    __syncthreads();

    u64 C[2][8];
    zeroC(C);
    gemmT(A1, g_WlhT, C, rowb, cg);
    gemmT(A2, g_WlaT, C, rowb, cg);          // accumulate second K-half

    float blv[16];
    loadbias16(b_lin, cg, blv);
    float v0[16], v1[16];
    unpackrow(C[0], v0);
    unpackrow(C[1], v1);
    float s0 = 0.f, s1 = 0.f;
#pragma unroll
    for (int c = 0; c < 16; ++c) {
        v0[c] = fmaxf(v0[c] + blv[c], 0.f); s0 += v0[c] * v0[c];
        v1[c] = fmaxf(v1[c] + blv[c], 0.f); s1 += v1[c] * v1[c];
    }
    ps[cg * TM + rowb]     = s0;
    ps[cg * TM + rowb + 1] = s1;
    __syncthreads();
    float t0 = 0.f, t1 = 0.f;
#pragma unroll
    for (int g = 0; g < 8; ++g) { t0 += ps[g * TM + rowb]; t1 += ps[g * TM + rowb + 1]; }
    const float rinv0 = 1.0f / fmaxf(sqrtf(t0), 1e-12f);
    const float rinv1 = 1.0f / fmaxf(sqrtf(t1), 1e-12f);
    float* d0 = out + (r0 + rowb) * WID + cg * 16;
    float* d1 = out + (r0 + rowb + 1) * WID + cg * 16;
#pragma unroll
    for (int q = 0; q < 4; ++q) {
        *(float4*)(d0 + q*4) = make_float4(v0[q*4]*rinv0, v0[q*4+1]*rinv0,
                                           v0[q*4+2]*rinv0, v0[q*4+3]*rinv0);
        *(float4*)(d1 + q*4) = make_float4(v1[q*4]*rinv1, v1[q*4+1]*rinv1,
                                           v1[q*4+2]*rinv1, v1[q*4+3]*rinv1);
    }
}

// ---------------- launch ----------------
extern "C" void kernel_launch(void* const* d_in, const int* in_sizes, int n_in,
                              void* d_out, int out_size) {
    const int*   nbd      = (const int*)d_in[0];
    const int*   node_idx = (const int*)d_in[1];
    const float* feats    = (const float*)d_in[2];
    const float* W_agg    = (const float*)d_in[3];
    const float* b_agg    = (const float*)d_in[4];
    const float* W_lin    = (const float*)d_in[5];
    const float* b_lin    = (const float*)d_in[6];
    float* out = (float*)d_out;

    cudaFuncSetAttribute(k_l2f, cudaFuncAttributeMaxDynamicSharedMemorySize, L2F_SMEM);

    k_init<<<(N_NODES + NT - 1) / NT, NT>>>(W_agg, W_lin);
    k_scatter<<<BATCH / NT, NT>>>(node_idx);
    k_batch<<<BATCH / TM, NT>>>(feats, b_agg);
    k_main<<<(N_NODES + TM - 1) / TM, NT>>>(nbd, b_agg, b_lin);
    k_agg2<<<BATCH / 8, NT>>>(nbd, node_idx);
    k_l2f<<<BATCH / TM, NT, L2F_SMEM>>>(node_idx, b_lin, out);
}